// round 12
// baseline (speedup 1.0000x reference)
#include <cuda_runtime.h>

// LoRALayerNorm: x [B=2, S=4096, N=8192] fp32 — ONE kernel, oversubscribed
// 8192-CTA grid (wave load-balancing beats persistent layouts on B300).
// CTAs 0..15 compute the rank-4 diag scale/shift vectors into device globals
// after issuing their own x loads. Every CTA issues its x loads FIRST, then
// tid0 spins on a 16-producer ready counter (overlapped by in-flight loads).
//
// R10 lesson: __ldg on same-launch-produced data gets hoisted above the spin
//             (non-coherent read-only path) -> stale zeros.
// R11 lesson: __ldcg bypasses L1, so sc/sh re-reads cost 512MB of L2 traffic
//             (8192 CTAs x 64KB) and starve DRAM. PLAIN loads are the answer:
//             generic ld.global.ca cannot be hoisted across __syncthreads()
//             and L1 persists across CTAs within the launch (~55 CTAs/SM hit).

#define N_FEAT 8192
#define N_ROWS 8192
#define RANK 4
#define SCALING_F 2.0f   // ALPHA/RANK = 8/4
#define EPS_F 1e-5f

#define TPB 512
#define VPT 4            // float4 per thread: 512*4*4 = 8192 floats per row
#define N_PROD 16        // producer CTAs: 16*512 threads = 8192 features

__device__ float g_scale[N_FEAT];
__device__ float g_shift[N_FEAT];
__device__ unsigned int g_ready = 0;   // producers arrived (0..16)
__device__ unsigned int g_done = 0;    // CTAs finished (reset mechanism)

__global__ __launch_bounds__(TPB, 3)
void lora_layernorm_fused_kernel(const float* __restrict__ x,
                                 const float* __restrict__ sA,
                                 const float* __restrict__ sB,
                                 const float* __restrict__ hA,
                                 const float* __restrict__ hB,
                                 float* __restrict__ out) {
    const int row = blockIdx.x;
    const int tid = threadIdx.x;
    const int wid = tid >> 5;
    const int lane = tid & 31;
    const float4* xrow = reinterpret_cast<const float4*>(x + (size_t)row * N_FEAT);
    float4* orow = reinterpret_cast<float4*>(out + (size_t)row * N_FEAT);

    // Issue this CTA's x loads first — in flight through phase 0 / spin /
    // the reduction.
    float4 v[VPT];
#pragma unroll
    for (int k = 0; k < VPT; k++) {
        v[k] = __ldcs(&xrow[tid + k * TPB]);
    }

    // ---- Phase 0 (producer CTAs only): sc/sh vectors, one feature/thread ----
    if (blockIdx.x < N_PROD) {
        const int i = blockIdx.x * TPB + tid;
        float4 a_s = __ldg(reinterpret_cast<const float4*>(sA + i * RANK));
        float4 a_h = __ldg(reinterpret_cast<const float4*>(hA + i * RANK));
        float sc = a_s.x * __ldg(&sB[0 * N_FEAT + i])
                 + a_s.y * __ldg(&sB[1 * N_FEAT + i])
                 + a_s.z * __ldg(&sB[2 * N_FEAT + i])
                 + a_s.w * __ldg(&sB[3 * N_FEAT + i]);
        float sh = a_h.x * __ldg(&hB[0 * N_FEAT + i])
                 + a_h.y * __ldg(&hB[1 * N_FEAT + i])
                 + a_h.z * __ldg(&hB[2 * N_FEAT + i])
                 + a_h.w * __ldg(&hB[3 * N_FEAT + i]);
        g_scale[i] = sc * SCALING_F;
        g_shift[i] = sh * SCALING_F;
        __threadfence();                 // release the vector writes
        __syncthreads();                 // all 512 features of this CTA done
        if (tid == 0) atomicAdd(&g_ready, 1u);
    }

    // ---- Reduction (overlaps the producers' phase 0) ----
    float sum = 0.0f, sumsq = 0.0f;
#pragma unroll
    for (int k = 0; k < VPT; k++) {
        float4 t = v[k];
        sum += t.x + t.y + t.z + t.w;
        sumsq += t.x * t.x + t.y * t.y + t.z * t.z + t.w * t.w;
    }
#pragma unroll
    for (int off = 16; off > 0; off >>= 1) {
        sum += __shfl_xor_sync(0xffffffffu, sum, off);
        sumsq += __shfl_xor_sync(0xffffffffu, sumsq, off);
    }

    __shared__ float s_sum[TPB / 32];
    __shared__ float s_sumsq[TPB / 32];
    __shared__ float s_mean, s_rstd;
    if (lane == 0) {
        s_sum[wid] = sum;
        s_sumsq[wid] = sumsq;
    }
    __syncthreads();
    if (wid == 0) {
        float a = (lane < TPB / 32) ? s_sum[lane] : 0.0f;
        float b = (lane < TPB / 32) ? s_sumsq[lane] : 0.0f;
#pragma unroll
        for (int off = 8; off > 0; off >>= 1) {
            a += __shfl_xor_sync(0xffffffffu, a, off);
            b += __shfl_xor_sync(0xffffffffu, b, off);
        }
        if (lane == 0) {
            float mean = a * (1.0f / N_FEAT);
            float var = b * (1.0f / N_FEAT) - mean * mean;
            s_mean = mean;
            s_rstd = rsqrtf(var + EPS_F);
        }
    }

    // ---- Wait for all 16 producers (tid 0 spins; usually already done) ----
    if (tid == 0) {
        while (*(volatile unsigned int*)&g_ready < N_PROD) { }
        __threadfence();                 // acquire before reading g_scale/shift
    }
    __syncthreads();
    const float mean = s_mean;
    const float rstd = s_rstd;

    // ---- Epilogue: PLAIN (.ca, L1-cached, non-hoistable) vector loads ----
    const float4* scv = reinterpret_cast<const float4*>(g_scale);
    const float4* shv = reinterpret_cast<const float4*>(g_shift);
#pragma unroll
    for (int k = 0; k < VPT; k++) {
        const int idx = tid + k * TPB;
        float4 sc = scv[idx];
        float4 sh = shv[idx];
        float4 t = v[k];
        float4 o;
        o.x = (t.x - mean) * rstd * sc.x + sh.x;
        o.y = (t.y - mean) * rstd * sc.y + sh.y;
        o.z = (t.z - mean) * rstd * sc.z + sh.z;
        o.w = (t.w - mean) * rstd * sc.w + sh.w;
        __stcs(&orow[idx], o);
    }

    // ---- Replay-safe reset: the LAST CTA to finish zeroes the flags. ----
    if (tid == 0) {
        unsigned int old = atomicAdd(&g_done, 1u);
        if (old == N_ROWS - 1) {
            atomicExch(&g_done, 0u);
            atomicExch(&g_ready, 0u);
        }
    }
}

// ---------------------------------------------------------------------------
extern "C" void kernel_launch(void* const* d_in, const int* in_sizes, int n_in,
                              void* d_out, int out_size) {
    const float* x = (const float*)d_in[0];
    const float* sA = (const float*)d_in[1];
    const float* sB = (const float*)d_in[2];
    const float* hA = (const float*)d_in[3];
    const float* hB = (const float*)d_in[4];
    float* out = (float*)d_out;

    lora_layernorm_fused_kernel<<<N_ROWS, TPB>>>(x, sA, sB, hA, hB, out);
}

// round 13
// speedup vs baseline: 1.1637x; 1.1637x over previous
#include <cuda_runtime.h>

// LoRALayerNorm: x [B=2, S=4096, N=8192] fp32 — ONE kernel, oversubscribed
// 8192-CTA grid. CTAs 0..15 compute the rank-4 diag scale/shift vectors into
// device globals; all CTAs issue x loads first, then tid0 spins on a
// 16-producer ready counter (overlapped by in-flight x loads).
//
// R10: __ldg on same-launch data hoists above the barrier (read-only path).
// R11: __ldcg bypasses L1 -> 512MB L2 refills of sc/sh.
// R12: consumer-side __threadfence() (gpu scope) emits CCTL.IVALL = FULL L1
//      FLUSH per CTA -> sc/sh never persist in L1 -> same 512MB L2 refills.
// R13: plain loads + NO gpu-scope fence on the consumer side. Ordering:
//      __syncthreads() is the compiler barrier (held for plain loads, proven
//      by R12 passing); producers release via __threadfence(); first touch
//      per SM is post-release so L1 can never hold stale copies.

#define N_FEAT 8192
#define N_ROWS 8192
#define RANK 4
#define SCALING_F 2.0f   // ALPHA/RANK = 8/4
#define EPS_F 1e-5f

#define TPB 512
#define VPT 4            // float4 per thread: 512*4*4 = 8192 floats per row
#define N_PROD 16        // producer CTAs: 16*512 threads = 8192 features

__device__ float g_scale[N_FEAT];
__device__ float g_shift[N_FEAT];
__device__ unsigned int g_ready = 0;   // producers arrived (0..16)
__device__ unsigned int g_done = 0;    // CTAs finished (reset mechanism)

__global__ __launch_bounds__(TPB, 3)
void lora_layernorm_fused_kernel(const float* __restrict__ x,
                                 const float* __restrict__ sA,
                                 const float* __restrict__ sB,
                                 const float* __restrict__ hA,
                                 const float* __restrict__ hB,
                                 float* __restrict__ out) {
    const int row = blockIdx.x;
    const int tid = threadIdx.x;
    const int wid = tid >> 5;
    const int lane = tid & 31;
    const float4* xrow = reinterpret_cast<const float4*>(x + (size_t)row * N_FEAT);
    float4* orow = reinterpret_cast<float4*>(out + (size_t)row * N_FEAT);

    // Issue this CTA's x loads first — in flight through phase 0 / spin /
    // the reduction.
    float4 v[VPT];
#pragma unroll
    for (int k = 0; k < VPT; k++) {
        v[k] = __ldcs(&xrow[tid + k * TPB]);
    }

    // ---- Phase 0 (producer CTAs only): sc/sh vectors, one feature/thread ----
    if (blockIdx.x < N_PROD) {
        const int i = blockIdx.x * TPB + tid;
        float4 a_s = __ldg(reinterpret_cast<const float4*>(sA + i * RANK));
        float4 a_h = __ldg(reinterpret_cast<const float4*>(hA + i * RANK));
        float sc = a_s.x * __ldg(&sB[0 * N_FEAT + i])
                 + a_s.y * __ldg(&sB[1 * N_FEAT + i])
                 + a_s.z * __ldg(&sB[2 * N_FEAT + i])
                 + a_s.w * __ldg(&sB[3 * N_FEAT + i]);
        float sh = a_h.x * __ldg(&hB[0 * N_FEAT + i])
                 + a_h.y * __ldg(&hB[1 * N_FEAT + i])
                 + a_h.z * __ldg(&hB[2 * N_FEAT + i])
                 + a_h.w * __ldg(&hB[3 * N_FEAT + i]);
        g_scale[i] = sc * SCALING_F;
        g_shift[i] = sh * SCALING_F;
        __threadfence();                 // release (16 CTAs only; cost ok)
        __syncthreads();                 // all 512 features of this CTA done
        if (tid == 0) atomicAdd(&g_ready, 1u);
    }

    // ---- Reduction (overlaps the producers' phase 0) ----
    float sum = 0.0f, sumsq = 0.0f;
#pragma unroll
    for (int k = 0; k < VPT; k++) {
        float4 t = v[k];
        sum += t.x + t.y + t.z + t.w;
        sumsq += t.x * t.x + t.y * t.y + t.z * t.z + t.w * t.w;
    }
#pragma unroll
    for (int off = 16; off > 0; off >>= 1) {
        sum += __shfl_xor_sync(0xffffffffu, sum, off);
        sumsq += __shfl_xor_sync(0xffffffffu, sumsq, off);
    }

    __shared__ float s_sum[TPB / 32];
    __shared__ float s_sumsq[TPB / 32];
    __shared__ float s_mean, s_rstd;
    if (lane == 0) {
        s_sum[wid] = sum;
        s_sumsq[wid] = sumsq;
    }
    __syncthreads();
    if (wid == 0) {
        float a = (lane < TPB / 32) ? s_sum[lane] : 0.0f;
        float b = (lane < TPB / 32) ? s_sumsq[lane] : 0.0f;
#pragma unroll
        for (int off = 8; off > 0; off >>= 1) {
            a += __shfl_xor_sync(0xffffffffu, a, off);
            b += __shfl_xor_sync(0xffffffffu, b, off);
        }
        if (lane == 0) {
            float mean = a * (1.0f / N_FEAT);
            float var = b * (1.0f / N_FEAT) - mean * mean;
            s_mean = mean;
            s_rstd = rsqrtf(var + EPS_F);
        }
    }

    // ---- Wait for all 16 producers (tid 0 spins; usually already done).
    // NO gpu-scope fence here (CCTL.IVALL would flush L1 and evict sc/sh
    // for every CTA). cta-scope fence + syncthreads give the ordering.
    if (tid == 0) {
        while (*(volatile unsigned int*)&g_ready < N_PROD) { }
        __threadfence_block();
    }
    __syncthreads();
    const float mean = s_mean;
    const float rstd = s_rstd;

    // ---- Epilogue: PLAIN (.ca, L1-persistent) vector loads ----
    const float4* scv = reinterpret_cast<const float4*>(g_scale);
    const float4* shv = reinterpret_cast<const float4*>(g_shift);
#pragma unroll
    for (int k = 0; k < VPT; k++) {
        const int idx = tid + k * TPB;
        float4 sc = scv[idx];
        float4 sh = shv[idx];
        float4 t = v[k];
        float4 o;
        o.x = (t.x - mean) * rstd * sc.x + sh.x;
        o.y = (t.y - mean) * rstd * sc.y + sh.y;
        o.z = (t.z - mean) * rstd * sc.z + sh.z;
        o.w = (t.w - mean) * rstd * sc.w + sh.w;
        __stcs(&orow[idx], o);
    }

    // ---- Replay-safe reset: the LAST CTA to finish zeroes the flags. ----
    if (tid == 0) {
        unsigned int old = atomicAdd(&g_done, 1u);
        if (old == N_ROWS - 1) {
            atomicExch(&g_done, 0u);
            atomicExch(&g_ready, 0u);
        }
    }
}

// ---------------------------------------------------------------------------
extern "C" void kernel_launch(void* const* d_in, const int* in_sizes, int n_in,
                              void* d_out, int out_size) {
    const float* x = (const float*)d_in[0];
    const float* sA = (const float*)d_in[1];
    const float* sB = (const float*)d_in[2];
    const float* hA = (const float*)d_in[3];
    const float* hB = (const float*)d_in[4];
    float* out = (float*)d_out;

    lora_layernorm_fused_kernel<<<N_ROWS, TPB>>>(x, sA, sB, hA, hB, out);
}

// round 14
// speedup vs baseline: 1.1895x; 1.0221x over previous
#include <cuda_runtime.h>

// LoRALayerNorm: x [B=2, S=4096, N=8192] fp32 — ONE kernel, oversubscribed
// 8192-CTA grid. CTAs 0..15 produce the rank-4 diag scale/shift vectors into
// device globals; every CTA issues its x loads first.
//
// Lessons: R10 __ldg hoists across barriers; R11 __ldcg kills L1 reuse;
// R12 consumer __threadfence() = CCTL.IVALL L1 flush kills reuse too;
// R13 plain loads + block fence correct but spin+returned-atomic cost ~8%.
// R14: monotonic epoch protocol (no reset, no returned atomic):
//   g_ready: cumulative producer arrivals (16 per launch).
//   g_spun:  cumulative CTAs past the spin (8192 per launch, REDG no-return).
//   launch index n = g_spun@entry / 8192 + 1  (exact: launches serialize).
//   consumer target = 16*n; early probe overlaps x-load latency so only
//   wave-1 CTAs ever take the late spin.

#define N_FEAT 8192
#define N_ROWS 8192
#define RANK 4
#define SCALING_F 2.0f   // ALPHA/RANK = 8/4
#define EPS_F 1e-5f

#define TPB 512
#define VPT 4            // float4 per thread: 512*4*4 = 8192 floats per row
#define N_PROD 16        // producer CTAs: 16*512 threads = 8192 features

__device__ float g_scale[N_FEAT];
__device__ float g_shift[N_FEAT];
__device__ unsigned int g_ready = 0;   // cumulative producer arrivals
__device__ unsigned int g_spun = 0;    // cumulative CTAs past the spin

__global__ __launch_bounds__(TPB, 3)
void lora_layernorm_fused_kernel(const float* __restrict__ x,
                                 const float* __restrict__ sA,
                                 const float* __restrict__ sB,
                                 const float* __restrict__ hA,
                                 const float* __restrict__ hB,
                                 float* __restrict__ out) {
    const int row = blockIdx.x;
    const int tid = threadIdx.x;
    const int wid = tid >> 5;
    const int lane = tid & 31;
    const float4* xrow = reinterpret_cast<const float4*>(x + (size_t)row * N_FEAT);
    float4* orow = reinterpret_cast<float4*>(out + (size_t)row * N_FEAT);

    // Issue this CTA's x loads first — in flight through everything below.
    float4 v[VPT];
#pragma unroll
    for (int k = 0; k < VPT; k++) {
        v[k] = __ldcs(&xrow[tid + k * TPB]);
    }

    // Early epoch read + readiness probe (overlapped by x-load latency).
    __shared__ unsigned int s_target;
    __shared__ int s_ok;
    if (tid == 0) {
        unsigned int spun = *(volatile unsigned int*)&g_spun;
        unsigned int target = ((spun >> 13) + 1u) * (unsigned)N_PROD;  // 8192 = 2^13
        s_target = target;
        s_ok = (*(volatile unsigned int*)&g_ready >= target) ? 1 : 0;
    }

    // ---- Phase 0 (producer CTAs only): sc/sh vectors, one feature/thread ----
    if (blockIdx.x < N_PROD) {
        const int i = blockIdx.x * TPB + tid;
        float4 a_s = __ldg(reinterpret_cast<const float4*>(sA + i * RANK));
        float4 a_h = __ldg(reinterpret_cast<const float4*>(hA + i * RANK));
        float sc = a_s.x * __ldg(&sB[0 * N_FEAT + i])
                 + a_s.y * __ldg(&sB[1 * N_FEAT + i])
                 + a_s.z * __ldg(&sB[2 * N_FEAT + i])
                 + a_s.w * __ldg(&sB[3 * N_FEAT + i]);
        float sh = a_h.x * __ldg(&hB[0 * N_FEAT + i])
                 + a_h.y * __ldg(&hB[1 * N_FEAT + i])
                 + a_h.z * __ldg(&hB[2 * N_FEAT + i])
                 + a_h.w * __ldg(&hB[3 * N_FEAT + i]);
        g_scale[i] = sc * SCALING_F;
        g_shift[i] = sh * SCALING_F;
        __threadfence();                 // release (16 CTAs only)
        __syncthreads();                 // all 512 features of this CTA done
        if (tid == 0) atomicAdd(&g_ready, 1u);
    }

    // ---- Reduction (overlaps producers' phase 0 and the early probe) ----
    float sum = 0.0f, sumsq = 0.0f;
#pragma unroll
    for (int k = 0; k < VPT; k++) {
        float4 t = v[k];
        sum += t.x + t.y + t.z + t.w;
        sumsq += t.x * t.x + t.y * t.y + t.z * t.z + t.w * t.w;
    }
#pragma unroll
    for (int off = 16; off > 0; off >>= 1) {
        sum += __shfl_xor_sync(0xffffffffu, sum, off);
        sumsq += __shfl_xor_sync(0xffffffffu, sumsq, off);
    }

    __shared__ float s_sum[TPB / 32];
    __shared__ float s_sumsq[TPB / 32];
    __shared__ float s_mean, s_rstd;
    if (lane == 0) {
        s_sum[wid] = sum;
        s_sumsq[wid] = sumsq;
    }
    __syncthreads();
    if (wid == 0) {
        float a = (lane < TPB / 32) ? s_sum[lane] : 0.0f;
        float b = (lane < TPB / 32) ? s_sumsq[lane] : 0.0f;
#pragma unroll
        for (int off = 8; off > 0; off >>= 1) {
            a += __shfl_xor_sync(0xffffffffu, a, off);
            b += __shfl_xor_sync(0xffffffffu, b, off);
        }
        if (lane == 0) {
            float mean = a * (1.0f / N_FEAT);
            float var = b * (1.0f / N_FEAT) - mean * mean;
            s_mean = mean;
            s_rstd = rsqrtf(var + EPS_F);
        }
    }

    // ---- Late spin ONLY if the early probe failed (wave-1 CTAs).
    // No gpu-scope fence (would CCTL.IVALL-flush L1 and evict sc/sh).
    if (tid == 0 && !s_ok) {
        const unsigned int target = s_target;
        while (*(volatile unsigned int*)&g_ready < target) { }
        __threadfence_block();
    }
    __syncthreads();
    const float mean = s_mean;
    const float rstd = s_rstd;

    // ---- Mark this CTA past the spin: fire-and-forget (REDG, no return) ----
    if (tid == 0) {
        atomicAdd(&g_spun, 1u);   // result unused -> RED, no wait
    }

    // ---- Epilogue: PLAIN (.ca, L1-persistent) vector loads ----
    const float4* scv = reinterpret_cast<const float4*>(g_scale);
    const float4* shv = reinterpret_cast<const float4*>(g_shift);
#pragma unroll
    for (int k = 0; k < VPT; k++) {
        const int idx = tid + k * TPB;
        float4 sc = scv[idx];
        float4 sh = shv[idx];
        float4 t = v[k];
        float4 o;
        o.x = (t.x - mean) * rstd * sc.x + sh.x;
        o.y = (t.y - mean) * rstd * sc.y + sh.y;
        o.z = (t.z - mean) * rstd * sc.z + sh.z;
        o.w = (t.w - mean) * rstd * sc.w + sh.w;
        __stcs(&orow[idx], o);
    }
}

// ---------------------------------------------------------------------------
extern "C" void kernel_launch(void* const* d_in, const int* in_sizes, int n_in,
                              void* d_out, int out_size) {
    const float* x = (const float*)d_in[0];
    const float* sA = (const float*)d_in[1];
    const float* sB = (const float*)d_in[2];
    const float* hA = (const float*)d_in[3];
    const float* hB = (const float*)d_in[4];
    float* out = (float*)d_out;

    lora_layernorm_fused_kernel<<<N_ROWS, TPB>>>(x, sA, sB, hA, hB, out);
}

// round 15
// speedup vs baseline: 1.2023x; 1.0108x over previous
#include <cuda_runtime.h>

// LoRALayerNorm: x [B=2, S=4096, N=8192] fp32.
// Two kernels overlapped via PDL (programmatic dependent launch):
//   k1 (64 CTAs x 128 thr): rank-4 diag -> g_scale/g_shift; wide + shallow so
//      its critical path is one load round-trip; triggers dependent launch
//      at the top.
//   k2 (8192 CTAs x 512): register-resident single-pass layernorm; issues its
//      x loads FIRST, then grid-dep-syncs on k1 while those loads are still
//      in flight (the wait is covered by DRAM latency + the reduction tree).
// Best measured body: 77.2us @ 6.2TB/s (the 1R:1W DRAM ceiling on B300).

#define N_FEAT 8192
#define N_ROWS 8192
#define RANK 4
#define SCALING_F 2.0f   // ALPHA/RANK = 8/4
#define EPS_F 1e-5f

#define TPB 512
#define VPT 4            // float4 per thread: 512*4*4 = 8192 floats per row

#define K1_TPB 128
#define K1_CTAS (N_FEAT / K1_TPB)   // 64 CTAs, one feature per thread

__device__ float g_scale[N_FEAT];
__device__ float g_shift[N_FEAT];

// ---------------------------------------------------------------------------
// Kernel 1: low-rank diagonal -> scale/shift vectors (wide & shallow)
// ---------------------------------------------------------------------------
__global__ __launch_bounds__(K1_TPB)
void compute_vectors_kernel(const float* __restrict__ sA,
                            const float* __restrict__ sB,
                            const float* __restrict__ hA,
                            const float* __restrict__ hB) {
    cudaTriggerProgrammaticLaunchCompletion();

    const int i = blockIdx.x * K1_TPB + threadIdx.x;
    float4 a_s = __ldg(reinterpret_cast<const float4*>(sA + i * RANK));
    float4 a_h = __ldg(reinterpret_cast<const float4*>(hA + i * RANK));
    float sc = a_s.x * __ldg(&sB[0 * N_FEAT + i])
             + a_s.y * __ldg(&sB[1 * N_FEAT + i])
             + a_s.z * __ldg(&sB[2 * N_FEAT + i])
             + a_s.w * __ldg(&sB[3 * N_FEAT + i]);
    float sh = a_h.x * __ldg(&hB[0 * N_FEAT + i])
             + a_h.y * __ldg(&hB[1 * N_FEAT + i])
             + a_h.z * __ldg(&hB[2 * N_FEAT + i])
             + a_h.w * __ldg(&hB[3 * N_FEAT + i]);
    g_scale[i] = sc * SCALING_F;
    g_shift[i] = sh * SCALING_F;
}

// ---------------------------------------------------------------------------
// Kernel 2: one CTA per row, register-resident single-pass layernorm.
// Grid-dep sync right after load ISSUE (overlapped by load latency).
// ---------------------------------------------------------------------------
__global__ __launch_bounds__(TPB, 3)
void lora_layernorm_kernel(const float* __restrict__ x,
                           float* __restrict__ out) {
    const int row = blockIdx.x;
    const int tid = threadIdx.x;
    const float4* xrow = reinterpret_cast<const float4*>(x + (size_t)row * N_FEAT);
    float4* orow = reinterpret_cast<float4*>(out + (size_t)row * N_FEAT);

    // Streaming loads of x — issued first, independent of kernel 1.
    float4 v[VPT];
#pragma unroll
    for (int k = 0; k < VPT; k++) {
        v[k] = __ldcs(&xrow[tid + k * TPB]);
    }

    // Wait for kernel 1 while our loads are in flight; no-op for waves >= 2.
    cudaGridDependencySynchronize();

    float sum = 0.0f, sumsq = 0.0f;
#pragma unroll
    for (int k = 0; k < VPT; k++) {
        float4 t = v[k];
        sum += t.x + t.y + t.z + t.w;
        sumsq += t.x * t.x + t.y * t.y + t.z * t.z + t.w * t.w;
    }

#pragma unroll
    for (int off = 16; off > 0; off >>= 1) {
        sum += __shfl_xor_sync(0xffffffffu, sum, off);
        sumsq += __shfl_xor_sync(0xffffffffu, sumsq, off);
    }

    __shared__ float s_sum[TPB / 32];
    __shared__ float s_sumsq[TPB / 32];
    __shared__ float s_mean, s_rstd;
    const int wid = tid >> 5;
    const int lane = tid & 31;
    if (lane == 0) {
        s_sum[wid] = sum;
        s_sumsq[wid] = sumsq;
    }
    __syncthreads();
    if (wid == 0) {
        float a = (lane < TPB / 32) ? s_sum[lane] : 0.0f;
        float b = (lane < TPB / 32) ? s_sumsq[lane] : 0.0f;
#pragma unroll
        for (int off = 8; off > 0; off >>= 1) {
            a += __shfl_xor_sync(0xffffffffu, a, off);
            b += __shfl_xor_sync(0xffffffffu, b, off);
        }
        if (lane == 0) {
            float mean = a * (1.0f / N_FEAT);
            float var = b * (1.0f / N_FEAT) - mean * mean;
            s_mean = mean;
            s_rstd = rsqrtf(var + EPS_F);
        }
    }
    __syncthreads();
    const float mean = s_mean;
    const float rstd = s_rstd;

    const float4* scv = reinterpret_cast<const float4*>(g_scale);
    const float4* shv = reinterpret_cast<const float4*>(g_shift);
#pragma unroll
    for (int k = 0; k < VPT; k++) {
        const int idx = tid + k * TPB;
        float4 sc = __ldg(&scv[idx]);
        float4 sh = __ldg(&shv[idx]);
        float4 t = v[k];
        float4 o;
        o.x = (t.x - mean) * rstd * sc.x + sh.x;
        o.y = (t.y - mean) * rstd * sc.y + sh.y;
        o.z = (t.z - mean) * rstd * sc.z + sh.z;
        o.w = (t.w - mean) * rstd * sc.w + sh.w;
        __stcs(&orow[idx], o);
    }
}

// ---------------------------------------------------------------------------
extern "C" void kernel_launch(void* const* d_in, const int* in_sizes, int n_in,
                              void* d_out, int out_size) {
    const float* x = (const float*)d_in[0];
    const float* sA = (const float*)d_in[1];
    const float* sB = (const float*)d_in[2];
    const float* hA = (const float*)d_in[3];
    const float* hB = (const float*)d_in[4];
    float* out = (float*)d_out;

    compute_vectors_kernel<<<K1_CTAS, K1_TPB>>>(sA, sB, hA, hB);

    cudaLaunchConfig_t cfg = {};
    cfg.gridDim = dim3(N_ROWS, 1, 1);
    cfg.blockDim = dim3(TPB, 1, 1);
    cfg.dynamicSmemBytes = 0;
    cfg.stream = 0;
    cudaLaunchAttribute attr[1];
    attr[0].id = cudaLaunchAttributeProgrammaticStreamSerialization;
    attr[0].val.programmaticStreamSerializationAllowed = 1;
    cfg.attrs = attr;
    cfg.numAttrs = 1;
    cudaLaunchKernelEx(&cfg, lora_layernorm_kernel, x, out);
}